// round 13
// baseline (speedup 1.0000x reference)
#include <cuda_runtime.h>
#include <cuda_fp16.h>
#include <stdint.h>

// Problem dims
#define Bb   32
#define Ss   2048
#define Ee   1024
#define Uu   1024
#define TOK  (Bb * Ss)          // 65536 tokens

// GEMM tiling
#define TM   128                 // compact tokens per CTA tile
#define TN   256                 // U columns per CTA (1 n-chunk)
#define KT   32                  // K tile (fp16 elements)
#define NKT  (Ee / KT)           // 32
#define NGR  4                   // n-groups (CTAs per m-tile)
#define NIT  NKT                 // 32 iterations per CTA
#define MT   320                 // max m-tiles launched (covers Nv <= 40960)

// Padded smem rows: 32 halfs + 8 pad = 40 halfs = 80 bytes (conflict-free ldmatrix)
#define ROWB 80

#define SM_A    0
#define SM_B    (TM * ROWB)                  // 10240
#define STAGE   (TM * ROWB + TN * ROWB)      // 30720
#define NSTAGE  5
#define SMEM_DYN (NSTAGE * STAGE)            // 153600

// ------------------------- device scratch -------------------------
__device__ __half g_Xh[(size_t)TOK * Ee];    // compact fp16 X rows (written by GEMM y=0)
__device__ __half g_Mh[Uu * Ee];             // 2 MB (L2-resident)
__device__ float g_score[TOK];               // compact scores
__device__ float g_alpha[TOK];               // compact alphas
__device__ int   g_tokb[TOK];                // per-batch local compaction (global token ids)
__device__ int   g_tok[TOK];                 // dense compact token ids
__device__ int   g_cnt[Bb];
__device__ int   g_off[Bb];
__device__ int   g_ntiles;

// ------------------------- helpers -------------------------
__device__ __forceinline__ uint32_t smem_u32(const void* p) {
    uint32_t a;
    asm("{ .reg .u64 t; cvta.to.shared.u64 t, %1; cvt.u32.u64 %0, t; }"
        : "=r"(a) : "l"(p));
    return a;
}
__device__ __forceinline__ void cp_async16(uint32_t dst_smem, const void* src) {
    asm volatile("cp.async.ca.shared.global [%0], [%1], 16;"
                 :: "r"(dst_smem), "l"(src) : "memory");
}
__device__ __forceinline__ void cp_commit() {
    asm volatile("cp.async.commit_group;" ::: "memory");
}
__device__ __forceinline__ void ldsm_x4(uint32_t* r, uint32_t addr) {
    asm volatile("ldmatrix.sync.aligned.m8n8.x4.shared.b16 {%0,%1,%2,%3}, [%4];"
                 : "=r"(r[0]), "=r"(r[1]), "=r"(r[2]), "=r"(r[3]) : "r"(addr));
}
__device__ __forceinline__ void mma16816(float* c, const uint32_t* a, uint32_t b0, uint32_t b1) {
    asm volatile(
        "mma.sync.aligned.m16n8k16.row.col.f32.f16.f16.f32 "
        "{%0,%1,%2,%3}, {%4,%5,%6,%7}, {%8,%9}, {%0,%1,%2,%3};"
        : "+f"(c[0]), "+f"(c[1]), "+f"(c[2]), "+f"(c[3])
        : "r"(a[0]), "r"(a[1]), "r"(a[2]), "r"(a[3]), "r"(b0), "r"(b1));
}
__device__ __forceinline__ float fast_tanh(float x) {
    float xc = fminf(fmaxf(x, -12.0f), 12.0f);
    float e = __expf(2.0f * xc);
    return __fdividef(e - 1.0f, e + 1.0f);
}
__device__ __forceinline__ uint32_t pack_h2(float a, float b) {
    __half2 h = __floats2half2_rn(a, b);
    return *(uint32_t*)&h;
}

// ------------------------- kernel 1: compact masks + convert M + zero scores -------------------------
__global__ void __launch_bounds__(1024) prep_kernel(const int* __restrict__ mask,
                                                    const float* __restrict__ W,
                                                    const float* __restrict__ Um) {
    __shared__ int wsum[32];
    const int b = blockIdx.x, t = threadIdx.x;
    const int lane = t & 31, w = t >> 5;

    // --- mask compaction (2 tokens per thread) ---
    const int* mb = mask + b * Ss;
    const int m0 = mb[2 * t] != 0;
    const int m1 = mb[2 * t + 1] != 0;
    const int c = m0 + m1;
    int x = c;
    #pragma unroll
    for (int o = 1; o < 32; o <<= 1) {
        int y = __shfl_up_sync(0xFFFFFFFFu, x, o);
        if (lane >= o) x += y;
    }
    const int wtot = __shfl_sync(0xFFFFFFFFu, x, 31);
    if (lane == 31) wsum[w] = x;

    g_score[b * Ss + t] = 0.0f;
    g_score[b * Ss + t + 1024] = 0.0f;

    __syncthreads();
    if (w == 0) {
        int y = wsum[lane];
        #pragma unroll
        for (int o = 1; o < 32; o <<= 1) {
            int z = __shfl_up_sync(0xFFFFFFFFu, y, o);
            if (lane >= o) y += z;
        }
        wsum[lane] = y;
    }
    __syncthreads();
    const int excl = (wsum[w] - wtot) + (x - c);
    const int base = b * Ss;
    if (m0) g_tokb[base + excl] = base + 2 * t;
    if (m1) g_tokb[base + excl + m0] = base + 2 * t + 1;
    if (t == 1023) g_cnt[b] = excl + c;

    // --- convert M chunk ---
    const int n4 = Uu * Ee / 4;               // 262144
    const int per = n4 / Bb;                  // 8192
    for (int i = b * per + t; i < (b + 1) * per; i += 1024) {
        float4 wv = ((const float4*)W)[i];
        float4 uv = ((const float4*)Um)[i];
        uint2 ph;
        ph.x = pack_h2(wv.x + uv.x, wv.y + uv.y);
        ph.y = pack_h2(wv.z + uv.z, wv.w + uv.w);
        ((uint2*)g_Mh)[i] = ph;
    }
}

// ------------------------- kernel 2: offsets (redundant per block) + gather + tail pad -------------------------
__global__ void __launch_bounds__(1024) gather_kernel() {
    __shared__ int cnt[Bb];
    const int b = blockIdx.x, t = threadIdx.x;
    if (t < Bb) cnt[t] = g_cnt[t];
    __syncthreads();

    int off = 0, nv = 0;
    #pragma unroll
    for (int i = 0; i < Bb; i++) {
        if (i < b) off += cnt[i];
        nv += cnt[i];
    }
    const int n = cnt[b];

    if (b == 0) {
        if (t < Bb) {
            int o = 0;
            for (int i = 0; i < t; i++) o += cnt[i];
            g_off[t] = o;
        }
        if (t == 0) g_ntiles = (nv + TM - 1) / TM;
    }

    for (int i = t; i < n; i += 1024) g_tok[off + i] = g_tokb[b * Ss + i];

    // tail padding with safe dummy token 0
    for (int i = nv + b * 1024 + t; i < MT * TM; i += Bb * 1024) g_tok[i] = 0;
}

// ------------------------- kernel 3: compacted fp16 GEMM + X-convert + tanh + v-dot -------------------------
// grid (MT, 4): blockIdx.x = compact m-tile, blockIdx.y = n-chunk.
// NOTE: register-critical. Identical to the 287us R9 version — do not perturb.
__global__ void __launch_bounds__(256, 1) gemm_score_kernel(const float* __restrict__ X,
                                                            const float* __restrict__ v) {
    const int mt = blockIdx.x;
    if (mt >= g_ntiles) return;   // uniform early exit, before any barrier

    extern __shared__ __align__(16) char dsm[];
    __shared__ float red[TM];

    const int tid  = threadIdx.x;
    const int wid  = tid >> 5;
    const int lane = tid & 31;
    const int wm   = wid & 1;   // 2 m-warps
    const int wn   = wid >> 1;  // 4 n-warps
    const int m0   = mt * TM;                 // compact row base
    const int n0   = blockIdx.y * TN;

    const uint32_t ub = smem_u32(dsm);

    const int ar0 = tid >> 2;
    const int ach = tid & 3;
    const int t0 = g_tok[m0 + ar0];
    const int t1 = g_tok[m0 + ar0 + 64];
    const float4* Xrow0 = (const float4*)(X + (size_t)t0 * Ee + ach * 8);
    const float4* Xrow1 = (const float4*)(X + (size_t)t1 * Ee + ach * 8);

    float4 xa[4];   // A staging for the next stage

    auto loadA = [&](int s) {
        const int k0q = s * (KT / 4);
        xa[0] = Xrow0[k0q];  xa[1] = Xrow0[k0q + 1];
        xa[2] = Xrow1[k0q];  xa[3] = Xrow1[k0q + 1];
    };
    auto stsA = [&](int s, int buf) {
        char* sbp = dsm + buf * STAGE;
        uint4 p0, p1;
        p0.x = pack_h2(xa[0].x, xa[0].y);  p0.y = pack_h2(xa[0].z, xa[0].w);
        p0.z = pack_h2(xa[1].x, xa[1].y);  p0.w = pack_h2(xa[1].z, xa[1].w);
        p1.x = pack_h2(xa[2].x, xa[2].y);  p1.y = pack_h2(xa[2].z, xa[2].w);
        p1.z = pack_h2(xa[3].x, xa[3].y);  p1.w = pack_h2(xa[3].z, xa[3].w);
        *(uint4*)(sbp + SM_A + ar0 * ROWB + ach * 16) = p0;
        *(uint4*)(sbp + SM_A + (ar0 + 64) * ROWB + ach * 16) = p1;
        if (blockIdx.y == 0) {   // stream compact fp16 rows for out_kernel
            const int k0 = s * KT;
            *(uint4*)(g_Xh + (size_t)(m0 + ar0) * Ee + k0 + ach * 8) = p0;
            *(uint4*)(g_Xh + (size_t)(m0 + ar0 + 64) * Ee + k0 + ach * 8) = p1;
        }
    };
    auto fillB = [&](int s, int buf) {
        const uint32_t sb = ub + buf * STAGE;
        const int k0 = s * KT;
        #pragma unroll
        for (int i = tid; i < TN * 4; i += 256) {
            int r = i >> 2, cch = i & 3;
            cp_async16(sb + SM_B + r * ROWB + cch * 16,
                       g_Mh + (size_t)(n0 + r) * Ee + k0 + cch * 8);
        }
    };

    float c[4][8][4];
    #pragma unroll
    for (int mf = 0; mf < 4; ++mf)
        #pragma unroll
        for (int nf = 0; nf < 8; ++nf)
            #pragma unroll
            for (int e = 0; e < 4; ++e) c[mf][nf][e] = 0.0f;

    #pragma unroll
    for (int s = 0; s < 4; ++s) {
        loadA(s);
        stsA(s, s);
        fillB(s, s);
        cp_commit();
    }
    loadA(4);

    int buf_cur = 0, buf_fill = 4;
    #pragma unroll 1
    for (int it = 0; it < NIT; ++it) {
        asm volatile("cp.async.wait_group 3;" ::: "memory");
        __syncthreads();

        if (it + 4 < NIT) {
            stsA(it + 4, buf_fill);
            fillB(it + 4, buf_fill);
        }
        cp_commit();
        if (it + 5 < NIT) loadA(it + 5);
        buf_fill = (buf_fill + 1 == NSTAGE) ? 0 : buf_fill + 1;

        const uint32_t sb = ub + buf_cur * STAGE;
        buf_cur = (buf_cur + 1 == NSTAGE) ? 0 : buf_cur + 1;

        #pragma unroll
        for (int kk = 0; kk < 2; ++kk) {
            uint32_t a[4][4], b[4][4];
            uint32_t abase = sb + SM_A + (wm * 64 + (lane & 15)) * ROWB
                           + kk * 32 + ((lane >> 4) << 4);
            #pragma unroll
            for (int mf = 0; mf < 4; ++mf) ldsm_x4(a[mf], abase + mf * 16 * ROWB);

            uint32_t bbase = sb + SM_B
                           + (wn * 64 + (lane & 7) + ((lane >> 4) << 3)) * ROWB
                           + kk * 32 + ((lane & 8) << 1);
            #pragma unroll
            for (int nb = 0; nb < 4; ++nb) ldsm_x4(b[nb], bbase + nb * 16 * ROWB);

            #pragma unroll
            for (int mf = 0; mf < 4; ++mf)
                #pragma unroll
                for (int nb = 0; nb < 4; ++nb) {
                    mma16816(c[mf][2 * nb],     a[mf], b[nb][0], b[nb][1]);
                    mma16816(c[mf][2 * nb + 1], a[mf], b[nb][2], b[nb][3]);
                }
        }
    }

    // ---- epilogue: tanh(C) . v chunk -> per-row partial scores ----
    float ps[8];
    #pragma unroll
    for (int i = 0; i < 8; i++) ps[i] = 0.0f;
    #pragma unroll
    for (int mf = 0; mf < 4; ++mf) {
        #pragma unroll
        for (int nf = 0; nf < 8; ++nf) {
            int ncol = n0 + wn * 64 + nf * 8 + ((lane & 3) << 1);
            float v0 = __ldg(v + ncol);
            float v1 = __ldg(v + ncol + 1);
            ps[mf * 2 + 0] += fast_tanh(c[mf][nf][0]) * v0 + fast_tanh(c[mf][nf][1]) * v1;
            ps[mf * 2 + 1] += fast_tanh(c[mf][nf][2]) * v0 + fast_tanh(c[mf][nf][3]) * v1;
        }
    }

    #pragma unroll
    for (int i = 0; i < 8; i++) {
        ps[i] += __shfl_xor_sync(0xFFFFFFFFu, ps[i], 1);
        ps[i] += __shfl_xor_sync(0xFFFFFFFFu, ps[i], 2);
    }
    __syncthreads();
    if (tid < TM) red[tid] = 0.0f;
    __syncthreads();
    if ((lane & 3) == 0) {
        #pragma unroll
        for (int mf = 0; mf < 4; ++mf) {
            #pragma unroll
            for (int h = 0; h < 2; ++h) {
                int r = wm * 64 + mf * 16 + h * 8 + (lane >> 2);
                atomicAdd(&red[r], ps[mf * 2 + h]);
            }
        }
    }
    __syncthreads();
    if (tid < TM) atomicAdd(&g_score[m0 + tid], red[tid]);
}

// ------------------------- kernel 4: softmax over compact segment per batch -------------------------
__global__ void __launch_bounds__(1024) softmax_kernel(float* __restrict__ out) {
    const int b = blockIdx.x, t = threadIdx.x;
    const int lane = t & 31, w = t >> 5;
    __shared__ float sh[Ss];
    __shared__ float r32[32];
    const int off = g_off[b], L = g_cnt[b];

    out[b * Ee + t] = 0.0f;   // zero for atomic out kernel (Ee == blockDim)

    float m = -1e30f;
    for (int i = t; i < L; i += 1024) {
        float sc = g_score[off + i];
        sh[i] = sc;
        m = fmaxf(m, sc);
    }
    #pragma unroll
    for (int o = 16; o; o >>= 1) m = fmaxf(m, __shfl_xor_sync(0xFFFFFFFFu, m, o));
    if (lane == 0) r32[w] = m;
    __syncthreads();
    if (t < 32) {
        m = r32[t];
        #pragma unroll
        for (int o = 16; o; o >>= 1) m = fmaxf(m, __shfl_xor_sync(0xFFFFFFFFu, m, o));
        r32[t] = m;
    }
    __syncthreads();
    const float mx = r32[0];
    __syncthreads();

    float sum = 0.0f;
    for (int i = t; i < L; i += 1024) {
        float e = __expf(sh[i] - mx);
        sh[i] = e;
        sum += e;
    }
    #pragma unroll
    for (int o = 16; o; o >>= 1) sum += __shfl_xor_sync(0xFFFFFFFFu, sum, o);
    if (lane == 0) r32[w] = sum;
    __syncthreads();
    if (t < 32) {
        sum = r32[t];
        #pragma unroll
        for (int o = 16; o; o >>= 1) sum += __shfl_xor_sync(0xFFFFFFFFu, sum, o);
        r32[t] = sum;
    }
    __syncthreads();
    const float inv = 1.0f / r32[0];
    for (int i = t; i < L; i += 1024) g_alpha[off + i] = sh[i] * inv;
}

// ------------------------- kernel 5: out[b,:] += sum over compact segment -------------------------
#define NY 128
#define SCHUNK 16
__global__ void out_kernel(float* __restrict__ out) {
    const int b  = blockIdx.x;
    const int i0 = blockIdx.y * SCHUNK;
    const int L  = g_cnt[b];
    if (i0 >= L) return;
    const int off = g_off[b];
    const int tid = threadIdx.x;          // 256 threads x 4 halfs = 1024 cols
    __shared__ float sa[SCHUNK];
    if (tid < SCHUNK) {
        int i = i0 + tid;
        sa[tid] = (i < L) ? g_alpha[off + i] : 0.0f;
    }
    __syncthreads();

    float4 acc = make_float4(0.f, 0.f, 0.f, 0.f);
    const uint2* xb = (const uint2*)(g_Xh + (size_t)(off + i0) * Ee) + tid;
    #pragma unroll 4
    for (int s = 0; s < SCHUNK; ++s) {
        float a = sa[s];
        if (a != 0.0f) {
            uint2 p = xb[(size_t)s * (Ee / 4)];
            float2 x01 = __half22float2(*(__half2*)&p.x);
            float2 x23 = __half22float2(*(__half2*)&p.y);
            acc.x += a * x01.x;  acc.y += a * x01.y;
            acc.z += a * x23.x;  acc.w += a * x23.y;
        }
    }
    float* o = out + b * Ee + tid * 4;
    atomicAdd(o + 0, acc.x);
    atomicAdd(o + 1, acc.y);
    atomicAdd(o + 2, acc.z);
    atomicAdd(o + 3, acc.w);
}

// ------------------------- launch -------------------------
extern "C" void kernel_launch(void* const* d_in, const int* in_sizes, int n_in,
                              void* d_out, int out_size) {
    const float* X    = (const float*)d_in[0];
    const int*   mask = (const int*)d_in[1];
    const float* W    = (const float*)d_in[2];
    const float* Um   = (const float*)d_in[3];
    const float* v    = (const float*)d_in[4];
    float* out = (float*)d_out;

    cudaFuncSetAttribute(gemm_score_kernel, cudaFuncAttributeMaxDynamicSharedMemorySize, SMEM_DYN);

    prep_kernel<<<Bb, 1024>>>(mask, W, Um);
    gather_kernel<<<Bb, 1024>>>();
    gemm_score_kernel<<<dim3(MT, NGR), 256, SMEM_DYN>>>(X, v);
    softmax_kernel<<<Bb, 1024>>>(out);
    out_kernel<<<dim3(Bb, NY), 256>>>(out);
}

// round 14
// speedup vs baseline: 1.0089x; 1.0089x over previous
#include <cuda_runtime.h>
#include <cuda_fp16.h>
#include <stdint.h>

// Problem dims
#define Bb   32
#define Ss   2048
#define Ee   1024
#define Uu   1024
#define TOK  (Bb * Ss)          // 65536 tokens

// GEMM tiling
#define TM   128                 // compact tokens per CTA tile
#define TN   256                 // U columns per CTA (1 n-chunk)
#define KT   32                  // K tile (fp16 elements)
#define NKT  (Ee / KT)           // 32
#define NGR  4                   // n-groups (CTAs per m-tile)
#define NIT  NKT                 // 32 iterations per CTA
#define MT   320                 // max m-tiles launched (covers Nv <= 40960)

// Padded smem rows: 32 halfs + 8 pad = 40 halfs = 80 bytes (conflict-free ldmatrix)
#define ROWB 80

#define SM_A    0
#define SM_B    (TM * ROWB)                  // 10240
#define STAGE   (TM * ROWB + TN * ROWB)      // 30720
#define NSTAGE  5
#define SMEM_DYN (NSTAGE * STAGE)            // 153600

// ------------------------- device scratch -------------------------
__device__ __half g_Xh[(size_t)TOK * Ee];    // compact fp16 X rows (written by GEMM y=0)
__device__ __half g_Mh[Uu * Ee];             // 2 MB (L2-resident)
__device__ float g_score[TOK];               // compact scores
__device__ float g_alpha[TOK];               // compact alphas
__device__ int   g_tokb[TOK];                // per-batch local compaction (global token ids)
__device__ int   g_tok[TOK];                 // dense compact token ids
__device__ int   g_cnt[Bb];
__device__ int   g_off[Bb];
__device__ int   g_ntiles;

// ------------------------- helpers -------------------------
__device__ __forceinline__ uint32_t smem_u32(const void* p) {
    uint32_t a;
    asm("{ .reg .u64 t; cvta.to.shared.u64 t, %1; cvt.u32.u64 %0, t; }"
        : "=r"(a) : "l"(p));
    return a;
}
__device__ __forceinline__ void cp_async16(uint32_t dst_smem, const void* src) {
    asm volatile("cp.async.ca.shared.global [%0], [%1], 16;"
                 :: "r"(dst_smem), "l"(src) : "memory");
}
__device__ __forceinline__ void cp_commit() {
    asm volatile("cp.async.commit_group;" ::: "memory");
}
__device__ __forceinline__ void ldsm_x4(uint32_t* r, uint32_t addr) {
    asm volatile("ldmatrix.sync.aligned.m8n8.x4.shared.b16 {%0,%1,%2,%3}, [%4];"
                 : "=r"(r[0]), "=r"(r[1]), "=r"(r[2]), "=r"(r[3]) : "r"(addr));
}
__device__ __forceinline__ void mma16816(float* c, const uint32_t* a, uint32_t b0, uint32_t b1) {
    asm volatile(
        "mma.sync.aligned.m16n8k16.row.col.f32.f16.f16.f32 "
        "{%0,%1,%2,%3}, {%4,%5,%6,%7}, {%8,%9}, {%0,%1,%2,%3};"
        : "+f"(c[0]), "+f"(c[1]), "+f"(c[2]), "+f"(c[3])
        : "r"(a[0]), "r"(a[1]), "r"(a[2]), "r"(a[3]), "r"(b0), "r"(b1));
}
__device__ __forceinline__ float fast_tanh(float x) {
    float xc = fminf(fmaxf(x, -12.0f), 12.0f);
    float e = __expf(2.0f * xc);
    return __fdividef(e - 1.0f, e + 1.0f);
}
__device__ __forceinline__ uint32_t pack_h2(float a, float b) {
    __half2 h = __floats2half2_rn(a, b);
    return *(uint32_t*)&h;
}

// ------------------------- kernel 1: compact masks + convert M + zero scores -------------------------
__global__ void __launch_bounds__(1024) prep_kernel(const int* __restrict__ mask,
                                                    const float* __restrict__ W,
                                                    const float* __restrict__ Um) {
    __shared__ int wsum[32];
    const int b = blockIdx.x, t = threadIdx.x;
    const int lane = t & 31, w = t >> 5;

    // --- mask compaction (2 tokens per thread) ---
    const int* mb = mask + b * Ss;
    const int m0 = mb[2 * t] != 0;
    const int m1 = mb[2 * t + 1] != 0;
    const int c = m0 + m1;
    int x = c;
    #pragma unroll
    for (int o = 1; o < 32; o <<= 1) {
        int y = __shfl_up_sync(0xFFFFFFFFu, x, o);
        if (lane >= o) x += y;
    }
    const int wtot = __shfl_sync(0xFFFFFFFFu, x, 31);
    if (lane == 31) wsum[w] = x;

    g_score[b * Ss + t] = 0.0f;
    g_score[b * Ss + t + 1024] = 0.0f;

    __syncthreads();
    if (w == 0) {
        int y = wsum[lane];
        #pragma unroll
        for (int o = 1; o < 32; o <<= 1) {
            int z = __shfl_up_sync(0xFFFFFFFFu, y, o);
            if (lane >= o) y += z;
        }
        wsum[lane] = y;
    }
    __syncthreads();
    const int excl = (wsum[w] - wtot) + (x - c);
    const int base = b * Ss;
    if (m0) g_tokb[base + excl] = base + 2 * t;
    if (m1) g_tokb[base + excl + m0] = base + 2 * t + 1;
    if (t == 1023) g_cnt[b] = excl + c;

    // --- convert M chunk ---
    const int n4 = Uu * Ee / 4;               // 262144
    const int per = n4 / Bb;                  // 8192
    for (int i = b * per + t; i < (b + 1) * per; i += 1024) {
        float4 wv = ((const float4*)W)[i];
        float4 uv = ((const float4*)Um)[i];
        uint2 ph;
        ph.x = pack_h2(wv.x + uv.x, wv.y + uv.y);
        ph.y = pack_h2(wv.z + uv.z, wv.w + uv.w);
        ((uint2*)g_Mh)[i] = ph;
    }
}

// ------------------------- kernel 2: offsets (redundant per block) + gather + tail pad -------------------------
__global__ void __launch_bounds__(1024) gather_kernel() {
    __shared__ int cnt[Bb];
    const int b = blockIdx.x, t = threadIdx.x;
    if (t < Bb) cnt[t] = g_cnt[t];
    __syncthreads();

    int off = 0, nv = 0;
    #pragma unroll
    for (int i = 0; i < Bb; i++) {
        if (i < b) off += cnt[i];
        nv += cnt[i];
    }
    const int n = cnt[b];

    if (b == 0) {
        if (t < Bb) {
            int o = 0;
            for (int i = 0; i < t; i++) o += cnt[i];
            g_off[t] = o;
        }
        if (t == 0) g_ntiles = (nv + TM - 1) / TM;
    }

    for (int i = t; i < n; i += 1024) g_tok[off + i] = g_tokb[b * Ss + i];

    // tail padding with safe dummy token 0
    for (int i = nv + b * 1024 + t; i < MT * TM; i += Bb * 1024) g_tok[i] = 0;
}

// ------------------------- kernel 3: compacted fp16 GEMM + X-convert + tanh + v-dot -------------------------
// grid (MT, 4): blockIdx.x = compact m-tile, blockIdx.y = n-chunk.
// NOTE: register-critical. Identical to the 287us R9 version — do not perturb.
__global__ void __launch_bounds__(256, 1) gemm_score_kernel(const float* __restrict__ X,
                                                            const float* __restrict__ v) {
    const int mt = blockIdx.x;
    if (mt >= g_ntiles) return;   // uniform early exit, before any barrier

    extern __shared__ __align__(16) char dsm[];
    __shared__ float red[TM];

    const int tid  = threadIdx.x;
    const int wid  = tid >> 5;
    const int lane = tid & 31;
    const int wm   = wid & 1;   // 2 m-warps
    const int wn   = wid >> 1;  // 4 n-warps
    const int m0   = mt * TM;                 // compact row base
    const int n0   = blockIdx.y * TN;

    const uint32_t ub = smem_u32(dsm);

    const int ar0 = tid >> 2;
    const int ach = tid & 3;
    const int t0 = g_tok[m0 + ar0];
    const int t1 = g_tok[m0 + ar0 + 64];
    const float4* Xrow0 = (const float4*)(X + (size_t)t0 * Ee + ach * 8);
    const float4* Xrow1 = (const float4*)(X + (size_t)t1 * Ee + ach * 8);

    float4 xa[4];   // A staging for the next stage

    auto loadA = [&](int s) {
        const int k0q = s * (KT / 4);
        xa[0] = Xrow0[k0q];  xa[1] = Xrow0[k0q + 1];
        xa[2] = Xrow1[k0q];  xa[3] = Xrow1[k0q + 1];
    };
    auto stsA = [&](int s, int buf) {
        char* sbp = dsm + buf * STAGE;
        uint4 p0, p1;
        p0.x = pack_h2(xa[0].x, xa[0].y);  p0.y = pack_h2(xa[0].z, xa[0].w);
        p0.z = pack_h2(xa[1].x, xa[1].y);  p0.w = pack_h2(xa[1].z, xa[1].w);
        p1.x = pack_h2(xa[2].x, xa[2].y);  p1.y = pack_h2(xa[2].z, xa[2].w);
        p1.z = pack_h2(xa[3].x, xa[3].y);  p1.w = pack_h2(xa[3].z, xa[3].w);
        *(uint4*)(sbp + SM_A + ar0 * ROWB + ach * 16) = p0;
        *(uint4*)(sbp + SM_A + (ar0 + 64) * ROWB + ach * 16) = p1;
        if (blockIdx.y == 0) {   // stream compact fp16 rows for out_kernel
            const int k0 = s * KT;
            *(uint4*)(g_Xh + (size_t)(m0 + ar0) * Ee + k0 + ach * 8) = p0;
            *(uint4*)(g_Xh + (size_t)(m0 + ar0 + 64) * Ee + k0 + ach * 8) = p1;
        }
    };
    auto fillB = [&](int s, int buf) {
        const uint32_t sb = ub + buf * STAGE;
        const int k0 = s * KT;
        #pragma unroll
        for (int i = tid; i < TN * 4; i += 256) {
            int r = i >> 2, cch = i & 3;
            cp_async16(sb + SM_B + r * ROWB + cch * 16,
                       g_Mh + (size_t)(n0 + r) * Ee + k0 + cch * 8);
        }
    };

    float c[4][8][4];
    #pragma unroll
    for (int mf = 0; mf < 4; ++mf)
        #pragma unroll
        for (int nf = 0; nf < 8; ++nf)
            #pragma unroll
            for (int e = 0; e < 4; ++e) c[mf][nf][e] = 0.0f;

    #pragma unroll
    for (int s = 0; s < 4; ++s) {
        loadA(s);
        stsA(s, s);
        fillB(s, s);
        cp_commit();
    }
    loadA(4);

    int buf_cur = 0, buf_fill = 4;
    #pragma unroll 1
    for (int it = 0; it < NIT; ++it) {
        asm volatile("cp.async.wait_group 3;" ::: "memory");
        __syncthreads();

        if (it + 4 < NIT) {
            stsA(it + 4, buf_fill);
            fillB(it + 4, buf_fill);
        }
        cp_commit();
        if (it + 5 < NIT) loadA(it + 5);
        buf_fill = (buf_fill + 1 == NSTAGE) ? 0 : buf_fill + 1;

        const uint32_t sb = ub + buf_cur * STAGE;
        buf_cur = (buf_cur + 1 == NSTAGE) ? 0 : buf_cur + 1;

        #pragma unroll
        for (int kk = 0; kk < 2; ++kk) {
            uint32_t a[4][4], b[4][4];
            uint32_t abase = sb + SM_A + (wm * 64 + (lane & 15)) * ROWB
                           + kk * 32 + ((lane >> 4) << 4);
            #pragma unroll
            for (int mf = 0; mf < 4; ++mf) ldsm_x4(a[mf], abase + mf * 16 * ROWB);

            uint32_t bbase = sb + SM_B
                           + (wn * 64 + (lane & 7) + ((lane >> 4) << 3)) * ROWB
                           + kk * 32 + ((lane & 8) << 1);
            #pragma unroll
            for (int nb = 0; nb < 4; ++nb) ldsm_x4(b[nb], bbase + nb * 16 * ROWB);

            #pragma unroll
            for (int mf = 0; mf < 4; ++mf)
                #pragma unroll
                for (int nb = 0; nb < 4; ++nb) {
                    mma16816(c[mf][2 * nb],     a[mf], b[nb][0], b[nb][1]);
                    mma16816(c[mf][2 * nb + 1], a[mf], b[nb][2], b[nb][3]);
                }
        }
    }

    // ---- epilogue: tanh(C) . v chunk -> per-row partial scores ----
    float ps[8];
    #pragma unroll
    for (int i = 0; i < 8; i++) ps[i] = 0.0f;
    #pragma unroll
    for (int mf = 0; mf < 4; ++mf) {
        #pragma unroll
        for (int nf = 0; nf < 8; ++nf) {
            int ncol = n0 + wn * 64 + nf * 8 + ((lane & 3) << 1);
            float v0 = __ldg(v + ncol);
            float v1 = __ldg(v + ncol + 1);
            ps[mf * 2 + 0] += fast_tanh(c[mf][nf][0]) * v0 + fast_tanh(c[mf][nf][1]) * v1;
            ps[mf * 2 + 1] += fast_tanh(c[mf][nf][2]) * v0 + fast_tanh(c[mf][nf][3]) * v1;
        }
    }

    #pragma unroll
    for (int i = 0; i < 8; i++) {
        ps[i] += __shfl_xor_sync(0xFFFFFFFFu, ps[i], 1);
        ps[i] += __shfl_xor_sync(0xFFFFFFFFu, ps[i], 2);
    }
    __syncthreads();
    if (tid < TM) red[tid] = 0.0f;
    __syncthreads();
    if ((lane & 3) == 0) {
        #pragma unroll
        for (int mf = 0; mf < 4; ++mf) {
            #pragma unroll
            for (int h = 0; h < 2; ++h) {
                int r = wm * 64 + mf * 16 + h * 8 + (lane >> 2);
                atomicAdd(&red[r], ps[mf * 2 + h]);
            }
        }
    }
    __syncthreads();
    if (tid < TM) atomicAdd(&g_score[m0 + tid], red[tid]);
}

// ------------------------- kernel 4: softmax over compact segment per batch -------------------------
__global__ void __launch_bounds__(1024) softmax_kernel(float* __restrict__ out) {
    const int b = blockIdx.x, t = threadIdx.x;
    const int lane = t & 31, w = t >> 5;
    __shared__ float sh[Ss];
    __shared__ float r32[32];
    const int off = g_off[b], L = g_cnt[b];

    out[b * Ee + t] = 0.0f;   // zero for atomic out kernel (Ee == blockDim)

    float m = -1e30f;
    for (int i = t; i < L; i += 1024) {
        float sc = g_score[off + i];
        sh[i] = sc;
        m = fmaxf(m, sc);
    }
    #pragma unroll
    for (int o = 16; o; o >>= 1) m = fmaxf(m, __shfl_xor_sync(0xFFFFFFFFu, m, o));
    if (lane == 0) r32[w] = m;
    __syncthreads();
    if (t < 32) {
        m = r32[t];
        #pragma unroll
        for (int o = 16; o; o >>= 1) m = fmaxf(m, __shfl_xor_sync(0xFFFFFFFFu, m, o));
        r32[t] = m;
    }
    __syncthreads();
    const float mx = r32[0];
    __syncthreads();

    float sum = 0.0f;
    for (int i = t; i < L; i += 1024) {
        float e = __expf(sh[i] - mx);
        sh[i] = e;
        sum += e;
    }
    #pragma unroll
    for (int o = 16; o; o >>= 1) sum += __shfl_xor_sync(0xFFFFFFFFu, sum, o);
    if (lane == 0) r32[w] = sum;
    __syncthreads();
    if (t < 32) {
        sum = r32[t];
        #pragma unroll
        for (int o = 16; o; o >>= 1) sum += __shfl_xor_sync(0xFFFFFFFFu, sum, o);
        r32[t] = sum;
    }
    __syncthreads();
    const float inv = 1.0f / r32[0];
    for (int i = t; i < L; i += 1024) g_alpha[off + i] = sh[i] * inv;
}

// ------------------------- kernel 5: out[b,:] += sum over compact segment -------------------------
#define NY 64
#define SCHUNK 32
__global__ void out_kernel(float* __restrict__ out) {
    const int b  = blockIdx.x;
    const int i0 = blockIdx.y * SCHUNK;
    const int L  = g_cnt[b];
    if (i0 >= L) return;
    const int off = g_off[b];
    const int tid = threadIdx.x;          // 256 threads x 4 halfs = 1024 cols
    __shared__ float sa[SCHUNK];
    if (tid < SCHUNK) {
        int i = i0 + tid;
        sa[tid] = (i < L) ? g_alpha[off + i] : 0.0f;
    }
    __syncthreads();

    float4 acc = make_float4(0.f, 0.f, 0.f, 0.f);
    const uint2* xb = (const uint2*)(g_Xh + (size_t)(off + i0) * Ee) + tid;
    #pragma unroll 4
    for (int s = 0; s < SCHUNK; ++s) {
        float a = sa[s];
        if (a != 0.0f) {
            uint2 p = xb[(size_t)s * (Ee / 4)];
            float2 x01 = __half22float2(*(__half2*)&p.x);
            float2 x23 = __half22float2(*(__half2*)&p.y);
            acc.x += a * x01.x;  acc.y += a * x01.y;
            acc.z += a * x23.x;  acc.w += a * x23.y;
        }
    }
    float* o = out + b * Ee + tid * 4;
    atomicAdd(o + 0, acc.x);
    atomicAdd(o + 1, acc.y);
    atomicAdd(o + 2, acc.z);
    atomicAdd(o + 3, acc.w);
}

// ------------------------- launch -------------------------
extern "C" void kernel_launch(void* const* d_in, const int* in_sizes, int n_in,
                              void* d_out, int out_size) {
    const float* X    = (const float*)d_in[0];
    const int*   mask = (const int*)d_in[1];
    const float* W    = (const float*)d_in[2];
    const float* Um   = (const float*)d_in[3];
    const float* v    = (const float*)d_in[4];
    float* out = (float*)d_out;

    cudaFuncSetAttribute(gemm_score_kernel, cudaFuncAttributeMaxDynamicSharedMemorySize, SMEM_DYN);

    prep_kernel<<<Bb, 1024>>>(mask, W, Um);
    gather_kernel<<<Bb, 1024>>>();
    gemm_score_kernel<<<dim3(MT, NGR), 256, SMEM_DYN>>>(X, v);
    softmax_kernel<<<Bb, 1024>>>(out);
    out_kernel<<<dim3(Bb, NY), 256>>>(out);
}